// round 13
// baseline (speedup 1.0000x reference)
#include <cuda_runtime.h>
#include <cuda_bf16.h>
#include <cstdint>

#define N_NODES 50000
#define N_EDGES 800000
#define D_IN    256
#define H_DIM   96
#define BN_EPS  1e-5f

#define BM 128
#define N_BLK 391          // ceil(50000/128)
#define PSTRIDE 400
#define KC 32              // k-chunk (fp32 elems)
#define PA 40              // smem row pitch in bf16 elems (80B, conflict-free)
#define EPB 32             // edges per scatter block

// ---------------- device scratch ----------------
__device__ __align__(16) float g_h0[N_NODES * H_DIM];
__device__ __align__(16) float g_z [N_NODES * H_DIM];
__device__ __align__(16) float g_h [N_NODES * H_DIM];
__device__ float g_psum [H_DIM * PSTRIDE];
__device__ float g_psq  [H_DIM * PSTRIDE];
__device__ float g_scale[H_DIM];
__device__ float g_shift[H_DIM];
__device__ int   g_is64;
__device__ int   g_done = 0;

// ---------------- smem layout (bytes into dynamic smem) ----------------
#define OFF_SCALE 0
#define OFF_SHIFT 384
#define OFF_A     768
#define A_HL      10240            // 128 rows * 40 elems * 2B
#define OFF_B     (OFF_A + 4 * A_HL)
#define B_HL      7680             // 96 * 40 * 2
#define SMEM_DYN  (OFF_B + 4 * B_HL)        // 72448

#define MMA(d, a, b) \
    asm volatile("mma.sync.aligned.m16n8k16.row.col.f32.bf16.bf16.f32 " \
                 "{%0,%1,%2,%3},{%4,%5,%6,%7},{%8,%9},{%0,%1,%2,%3};" \
                 : "+f"(d[0]), "+f"(d[1]), "+f"(d[2]), "+f"(d[3]) \
                 : "r"(a[0]), "r"(a[1]), "r"(a[2]), "r"(a[3]), "r"(b[0]), "r"(b[1]))

__device__ __forceinline__ uint32_t pack_hi(float v0, float v1, float& r0, float& r1) {
    __nv_bfloat162 hp = __floats2bfloat162_rn(v0, v1);
    r0 = __bfloat162float(__low2bfloat16(hp));
    r1 = __bfloat162float(__high2bfloat16(hp));
    return *reinterpret_cast<uint32_t*>(&hp);
}

// =====================================================================
// Split-bf16 tensor-core GEMM via mma.sync:
//   out[N,96] = A[N,KD] @ W[96,KD]^T + bias
// MODE 0: A = x -> g_h0, g_z   (+ edge dtype probe in block 0)
// MODE 1: A = g_z -> g_h + BN partials; LAST block -> scale/shift
// MODE 2: A = g_h (BN+ReLU on load) -> out
// =====================================================================
template<int KD, int MODE>
__global__ __launch_bounds__(256) void k_tgemm(const float* __restrict__ A_,
                                               const float* __restrict__ W,
                                               const float* __restrict__ bias,
                                               float* __restrict__ out,
                                               const int* __restrict__ ei32,
                                               const float* __restrict__ gamma,
                                               const float* __restrict__ beta) {
    constexpr int NC = KD / KC;
    extern __shared__ char smem[];

    const int tid    = threadIdx.x;
    const int lane   = tid & 31;
    const int wid    = tid >> 5;
    const int warp_m = wid >> 1;
    const int warp_n = wid & 1;
    const int g      = lane >> 2;
    const int t4     = lane & 3;
    const int row0   = blockIdx.x * BM;

    float* s_scale = (float*)(smem + OFF_SCALE);
    float* s_shift = (float*)(smem + OFF_SHIFT);
    __shared__ int s_last;

    if (MODE == 0 && blockIdx.x == 0 && tid == 0) {
        int nz = 0;
#pragma unroll
        for (int i = 0; i < 64; i++) nz |= ei32[2 * i + 1];
        g_is64 = (nz == 0) ? 1 : 0;
        g_done = 0;
    }
    if (MODE == 2 && tid < H_DIM) {
        s_scale[tid] = g_scale[tid];
        s_shift[tid] = g_shift[tid];
    }
    __syncthreads();

    const float* Ap = (MODE == 0) ? A_ : (MODE == 1 ? g_z : g_h);

    auto pAh = [&](int b) { return (char*)smem + OFF_A + b * 2 * A_HL; };
    auto pAl = [&](int b) { return (char*)smem + OFF_A + b * 2 * A_HL + A_HL; };
    auto pBh = [&](int b) { return (char*)smem + OFF_B + b * 2 * B_HL; };
    auto pBl = [&](int b) { return (char*)smem + OFF_B + b * 2 * B_HL + B_HL; };

    const int arow  = tid >> 1;
    const int ahalf = (tid & 1) * 16;
    float ra[16];
    float rb[12];

    auto ldgA = [&](int c) {
        const int gr = row0 + arow;
        const int kb = c * KC + ahalf;
        if (gr < N_NODES) {
#pragma unroll
            for (int q = 0; q < 4; q++) {
                float4 f = *reinterpret_cast<const float4*>(&Ap[(size_t)gr * KD + kb + q * 4]);
                ra[q*4+0] = f.x; ra[q*4+1] = f.y; ra[q*4+2] = f.z; ra[q*4+3] = f.w;
            }
            if (MODE == 2) {
#pragma unroll
                for (int q = 0; q < 16; q++)
                    ra[q] = fmaxf(ra[q] * s_scale[kb + q] + s_shift[kb + q], 0.f);
            }
        } else {
#pragma unroll
            for (int q = 0; q < 16; q++) ra[q] = 0.f;
        }
    };
    auto stsA = [&](int b) {
        char* ah = pAh(b);
        char* al = pAl(b);
#pragma unroll
        for (int j = 0; j < 8; j++) {
            float v0 = ra[2*j], v1 = ra[2*j+1], h0, h1;
            uint32_t hp = pack_hi(v0, v1, h0, h1);
            __nv_bfloat162 lo2 = __floats2bfloat162_rn(v0 - h0, v1 - h1);
            int boff = (arow * PA + ahalf + 2*j) * 2;
            *reinterpret_cast<uint32_t*>(ah + boff) = hp;
            *reinterpret_cast<uint32_t*>(al + boff) = *reinterpret_cast<uint32_t*>(&lo2);
        }
    };
    auto ldgB = [&](int c) {
#pragma unroll
        for (int q = 0; q < 3; q++) {
            int f4 = tid + q * 256;
            int rw = f4 >> 3;
            int kq = (f4 & 7) * 4;
            float4 f = *reinterpret_cast<const float4*>(&W[(size_t)rw * KD + c * KC + kq]);
            rb[q*4+0] = f.x; rb[q*4+1] = f.y; rb[q*4+2] = f.z; rb[q*4+3] = f.w;
        }
    };
    auto stsB = [&](int b) {
        char* bh = pBh(b);
        char* bl = pBl(b);
#pragma unroll
        for (int q = 0; q < 3; q++) {
            int f4 = tid + q * 256;
            int rw = f4 >> 3;
            int kq = (f4 & 7) * 4;
#pragma unroll
            for (int j = 0; j < 2; j++) {
                float v0 = rb[q*4 + 2*j], v1 = rb[q*4 + 2*j + 1], h0, h1;
                uint32_t hp = pack_hi(v0, v1, h0, h1);
                __nv_bfloat162 lo2 = __floats2bfloat162_rn(v0 - h0, v1 - h1);
                int boff = (rw * PA + kq + 2*j) * 2;
                *reinterpret_cast<uint32_t*>(bh + boff) = hp;
                *reinterpret_cast<uint32_t*>(bl + boff) = *reinterpret_cast<uint32_t*>(&lo2);
            }
        }
    };

    float acc[2][6][4];
#pragma unroll
    for (int mt = 0; mt < 2; mt++)
#pragma unroll
        for (int nt = 0; nt < 6; nt++)
#pragma unroll
            for (int q = 0; q < 4; q++) acc[mt][nt][q] = 0.f;

    auto compute = [&](int b) {
        const char* Ah = pAh(b);
        const char* Al = pAl(b);
        const char* Bh = pBh(b);
        const char* Bl = pBl(b);
#pragma unroll
        for (int kk = 0; kk < KC; kk += 16) {
            uint32_t ah[2][4], al[2][4], bh[6][2], bl[6][2];
#pragma unroll
            for (int mt = 0; mt < 2; mt++) {
                int r0 = warp_m * 32 + mt * 16 + g;
                int e0 = (r0 * PA + kk + t4 * 2) * 2;
                int e1 = ((r0 + 8) * PA + kk + t4 * 2) * 2;
                ah[mt][0] = *reinterpret_cast<const uint32_t*>(Ah + e0);
                ah[mt][1] = *reinterpret_cast<const uint32_t*>(Ah + e1);
                ah[mt][2] = *reinterpret_cast<const uint32_t*>(Ah + e0 + 16);
                ah[mt][3] = *reinterpret_cast<const uint32_t*>(Ah + e1 + 16);
                al[mt][0] = *reinterpret_cast<const uint32_t*>(Al + e0);
                al[mt][1] = *reinterpret_cast<const uint32_t*>(Al + e1);
                al[mt][2] = *reinterpret_cast<const uint32_t*>(Al + e0 + 16);
                al[mt][3] = *reinterpret_cast<const uint32_t*>(Al + e1 + 16);
            }
#pragma unroll
            for (int nt = 0; nt < 6; nt++) {
                int n = warp_n * 48 + nt * 8 + g;
                int e = (n * PA + kk + t4 * 2) * 2;
                bh[nt][0] = *reinterpret_cast<const uint32_t*>(Bh + e);
                bh[nt][1] = *reinterpret_cast<const uint32_t*>(Bh + e + 16);
                bl[nt][0] = *reinterpret_cast<const uint32_t*>(Bl + e);
                bl[nt][1] = *reinterpret_cast<const uint32_t*>(Bl + e + 16);
            }
#pragma unroll
            for (int mt = 0; mt < 2; mt++)
#pragma unroll
                for (int nt = 0; nt < 6; nt++) {
                    MMA(acc[mt][nt], ah[mt], bh[nt]);
                    MMA(acc[mt][nt], al[mt], bh[nt]);
                    MMA(acc[mt][nt], ah[mt], bl[nt]);
                }
        }
    };

    ldgA(0); ldgB(0);
    stsA(0); stsB(0);
    __syncthreads();
    for (int c = 0; c < NC; c++) {
        const bool pf = (c + 1 < NC);
        if (pf) { ldgA(c + 1); ldgB(c + 1); }
        compute(c & 1);
        if (pf) {
            stsA((c + 1) & 1); stsB((c + 1) & 1);
            __syncthreads();
        }
    }
    __syncthreads();

    // ---- epilogue: acc -> smem staging (pitch 100 floats) ----
    float* sD = (float*)(smem + OFF_A);
#pragma unroll
    for (int mt = 0; mt < 2; mt++) {
        int r0 = warp_m * 32 + mt * 16 + g;
#pragma unroll
        for (int nt = 0; nt < 6; nt++) {
            int cb = warp_n * 48 + nt * 8 + t4 * 2;
            sD[r0 * 100 + cb]       = acc[mt][nt][0];
            sD[r0 * 100 + cb + 1]   = acc[mt][nt][1];
            sD[(r0+8) * 100 + cb]   = acc[mt][nt][2];
            sD[(r0+8) * 100 + cb+1] = acc[mt][nt][3];
        }
    }
    __syncthreads();

    const int rmax = min(BM, N_NODES - row0);

    if (MODE == 1) {
        // BN partials: 192 threads, 2 row-halves per column
        __shared__ float s2sum[2][H_DIM], s2sq[2][H_DIM];
        if (tid < 2 * H_DIM) {
            const int c    = tid % H_DIM;
            const int half = tid / H_DIM;
            const float b  = bias[c];
            const int rlo  = half * 64;
            const int rhi  = min(rmax, rlo + 64);
            float s = 0.f, q = 0.f;
            for (int r = rlo; r < rhi; r++) {
                float v = sD[r * 100 + c] + b;
                s += v; q += v * v;
            }
            s2sum[half][c] = s; s2sq[half][c] = q;
        }
        __syncthreads();
        if (tid < H_DIM) {
            g_psum[tid * PSTRIDE + blockIdx.x] = s2sum[0][tid] + s2sum[1][tid];
            g_psq [tid * PSTRIDE + blockIdx.x] = s2sq [0][tid] + s2sq [1][tid];
        }
    }

    for (int idx = tid; idx < rmax * 24; idx += 256) {
        int r = idx / 24, c4 = idx % 24;
        float4 v = *reinterpret_cast<const float4*>(&sD[r * 100 + c4 * 4]);
        float4 b = *reinterpret_cast<const float4*>(&bias[c4 * 4]);
        v.x += b.x; v.y += b.y; v.z += b.z; v.w += b.w;
        size_t o = (size_t)(row0 + r) * H_DIM + c4 * 4;
        if (MODE == 0) {
            *reinterpret_cast<float4*>(&g_h0[o]) = v;
            *reinterpret_cast<float4*>(&g_z [o]) = v;
        } else if (MODE == 1) {
            *reinterpret_cast<float4*>(&g_h[o]) = v;
        } else {
            *reinterpret_cast<float4*>(&out[o]) = v;
        }
    }

    if (MODE == 1) {
        // last finishing block reduces partials -> scale/shift
        __threadfence();
        __syncthreads();
        if (tid == 0) s_last = (atomicAdd(&g_done, 1) == N_BLK - 1) ? 1 : 0;
        __syncthreads();
        if (s_last) {
            if (tid < H_DIM) {
                float s = 0.f, q = 0.f;
                for (int b = 0; b < N_BLK; b++) {
                    s += g_psum[tid * PSTRIDE + b];
                    q += g_psq [tid * PSTRIDE + b];
                }
                const float inv_n = 1.0f / (float)N_NODES;
                float mu  = s * inv_n;
                float var = q * inv_n - mu * mu;
                float sc  = gamma[tid] * rsqrtf(var + BN_EPS);
                g_scale[tid] = sc;
                g_shift[tid] = beta[tid] - mu * sc;
            }
            if (tid == 0) g_done = 0;
        }
    }
}

// =====================================================================
// Scatter-add  z[dst] += h0[src].  Block = 32 edges; indices staged in
// smem once; each thread: 3 col-groups (float4) of its edge.
// =====================================================================
__global__ __launch_bounds__(256) void k_scatter(const void* __restrict__ ei) {
    __shared__ int s_src[EPB], s_dst[EPB];
    const int tid = threadIdx.x;
    const int e0  = blockIdx.x * EPB;

    if (tid < 2 * EPB) {
        const int which = tid >> 5;          // 0: src, 1: dst
        const int i     = tid & 31;
        const int e     = e0 + i;
        int v = -1;
        if (e < N_EDGES) {
            const size_t off = which ? (size_t)N_EDGES + e : (size_t)e;
            v = g_is64 ? (int)((const long long*)ei)[off]
                       : ((const int*)ei)[off];
        }
        if (which) s_dst[i] = v; else s_src[i] = v;
    }
    __syncthreads();

    const int eL = tid >> 3;                 // 0..31
    const int c8 = tid & 7;                  // 0..7
    if (e0 + eL >= N_EDGES) return;
    const int src = s_src[eL];
    const int dst = s_dst[eL];
    if ((unsigned)src >= N_NODES || (unsigned)dst >= N_NODES) return;

    const float* srow = &g_h0[(size_t)src * H_DIM];
    float*       drow = &g_z [(size_t)dst * H_DIM];
#pragma unroll
    for (int j = 0; j < 3; j++) {
        const int c = (c8 + j * 8) * 4;
        const float4 v = *reinterpret_cast<const float4*>(srow + c);
        asm volatile("red.global.add.v4.f32 [%0], {%1,%2,%3,%4};"
                     :: "l"(drow + c), "f"(v.x), "f"(v.y), "f"(v.z), "f"(v.w)
                     : "memory");
    }
}

// =====================================================================
// launch
// =====================================================================
extern "C" void kernel_launch(void* const* d_in, const int* in_sizes, int n_in,
                              void* d_out, int out_size) {
    const float* x     = (const float*)d_in[0];
    const void*  ei    = d_in[1];
    const float* W0    = (const float*)d_in[2];
    const float* b0    = (const float*)d_in[3];
    const float* W1    = (const float*)d_in[4];
    const float* b1    = (const float*)d_in[5];
    const float* gamma = (const float*)d_in[6];
    const float* beta  = (const float*)d_in[7];
    const float* W2    = (const float*)d_in[8];
    const float* b2    = (const float*)d_in[9];
    float*       out   = (float*)d_out;

    static bool attr_done = false;
    if (!attr_done) {
        cudaFuncSetAttribute(k_tgemm<D_IN, 0>, cudaFuncAttributeMaxDynamicSharedMemorySize, SMEM_DYN);
        cudaFuncSetAttribute(k_tgemm<H_DIM, 1>, cudaFuncAttributeMaxDynamicSharedMemorySize, SMEM_DYN);
        cudaFuncSetAttribute(k_tgemm<H_DIM, 2>, cudaFuncAttributeMaxDynamicSharedMemorySize, SMEM_DYN);
        attr_done = true;
    }

    const int scat_blocks = (N_EDGES + EPB - 1) / EPB;   // 25000

    k_tgemm<D_IN, 0><<<N_BLK, 256, SMEM_DYN>>>(x, W0, b0, nullptr, (const int*)ei, nullptr, nullptr);
    k_scatter<<<scat_blocks, 256>>>(ei);
    k_tgemm<H_DIM, 1><<<N_BLK, 256, SMEM_DYN>>>(nullptr, W1, b1, nullptr, nullptr, gamma, beta);
    k_tgemm<H_DIM, 2><<<N_BLK, 256, SMEM_DYN>>>(nullptr, W2, b2, out, nullptr, nullptr, nullptr);
}

// round 14
// speedup vs baseline: 1.2056x; 1.2056x over previous
#include <cuda_runtime.h>
#include <cuda_bf16.h>
#include <cstdint>

#define N_NODES 50000
#define N_EDGES 800000
#define D_IN    256
#define H_DIM   96
#define BN_EPS  1e-5f

#define BM 128
#define N_BLK 391          // ceil(50000/128)
#define KC 32              // k-chunk (fp32 elems)
#define PA 40              // smem row pitch in bf16 elems (80B, conflict-free)
#define EPB 32             // edges per scatter block

// ---------------- device scratch ----------------
__device__ __align__(16) float g_h0[N_NODES * H_DIM];
__device__ __align__(16) float g_z [N_NODES * H_DIM];
__device__ __align__(16) float g_h [N_NODES * H_DIM];
__device__ float g_sum  [H_DIM];
__device__ float g_sumsq[H_DIM];
__device__ int   g_is64;

// ---------------- smem layout (bytes into dynamic smem) ----------------
#define OFF_SCALE 0
#define OFF_SHIFT 384
#define OFF_A     768
#define A_HL      10240            // 128 rows * 40 elems * 2B
#define OFF_B     (OFF_A + 4 * A_HL)
#define B_HL      7680             // 96 * 40 * 2
#define SMEM_DYN  (OFF_B + 4 * B_HL)        // 72448

#define MMA(d, a, b) \
    asm volatile("mma.sync.aligned.m16n8k16.row.col.f32.bf16.bf16.f32 " \
                 "{%0,%1,%2,%3},{%4,%5,%6,%7},{%8,%9},{%0,%1,%2,%3};" \
                 : "+f"(d[0]), "+f"(d[1]), "+f"(d[2]), "+f"(d[3]) \
                 : "r"(a[0]), "r"(a[1]), "r"(a[2]), "r"(a[3]), "r"(b[0]), "r"(b[1]))

__device__ __forceinline__ uint32_t pack_hi(float v0, float v1, float& r0, float& r1) {
    __nv_bfloat162 hp = __floats2bfloat162_rn(v0, v1);
    r0 = __bfloat162float(__low2bfloat16(hp));
    r1 = __bfloat162float(__high2bfloat16(hp));
    return *reinterpret_cast<uint32_t*>(&hp);
}

// =====================================================================
// Split-bf16 tensor-core GEMM via mma.sync:
//   out[N,96] = A[N,KD] @ W[96,KD]^T + bias
// MODE 0: A = x -> g_h0, g_z   (+ dtype probe & stat-zero in block 0)
// MODE 1: A = g_z -> g_h; BN partials atomically into g_sum/g_sumsq
// MODE 2: A = g_h (BN+ReLU on load; scale/shift computed per block) -> out
// =====================================================================
template<int KD, int MODE>
__global__ __launch_bounds__(256) void k_tgemm(const float* __restrict__ A_,
                                               const float* __restrict__ W,
                                               const float* __restrict__ bias,
                                               float* __restrict__ out,
                                               const int* __restrict__ ei32,
                                               const float* __restrict__ gamma,
                                               const float* __restrict__ beta) {
    constexpr int NC = KD / KC;
    extern __shared__ char smem[];

    const int tid    = threadIdx.x;
    const int lane   = tid & 31;
    const int wid    = tid >> 5;
    const int warp_m = wid >> 1;
    const int warp_n = wid & 1;
    const int g      = lane >> 2;
    const int t4     = lane & 3;
    const int row0   = blockIdx.x * BM;

    float* s_scale = (float*)(smem + OFF_SCALE);
    float* s_shift = (float*)(smem + OFF_SHIFT);

    if (MODE == 0 && blockIdx.x == 0) {
        if (tid < H_DIM) { g_sum[tid] = 0.f; g_sumsq[tid] = 0.f; }
        if (tid == 0) {
            int nz = 0;
#pragma unroll
            for (int i = 0; i < 64; i++) nz |= ei32[2 * i + 1];
            g_is64 = (nz == 0) ? 1 : 0;
        }
    }
    if (MODE == 2 && tid < H_DIM) {
        // per-block BN finalize: 192 L2 reads + rsqrt, replaces k_finalize kernel
        const float inv_n = 1.0f / (float)N_NODES;
        float mu  = g_sum[tid] * inv_n;
        float var = g_sumsq[tid] * inv_n - mu * mu;
        float sc  = gamma[tid] * rsqrtf(var + BN_EPS);
        s_scale[tid] = sc;
        s_shift[tid] = beta[tid] - mu * sc;
    }
    __syncthreads();

    const float* Ap = (MODE == 0) ? A_ : (MODE == 1 ? g_z : g_h);

    auto pAh = [&](int b) { return (char*)smem + OFF_A + b * 2 * A_HL; };
    auto pAl = [&](int b) { return (char*)smem + OFF_A + b * 2 * A_HL + A_HL; };
    auto pBh = [&](int b) { return (char*)smem + OFF_B + b * 2 * B_HL; };
    auto pBl = [&](int b) { return (char*)smem + OFF_B + b * 2 * B_HL + B_HL; };

    const int arow  = tid >> 1;
    const int ahalf = (tid & 1) * 16;
    float ra[16];
    float rb[12];

    auto ldgA = [&](int c) {
        const int gr = row0 + arow;
        const int kb = c * KC + ahalf;
        if (gr < N_NODES) {
#pragma unroll
            for (int q = 0; q < 4; q++) {
                float4 f = *reinterpret_cast<const float4*>(&Ap[(size_t)gr * KD + kb + q * 4]);
                ra[q*4+0] = f.x; ra[q*4+1] = f.y; ra[q*4+2] = f.z; ra[q*4+3] = f.w;
            }
            if (MODE == 2) {
#pragma unroll
                for (int q = 0; q < 16; q++)
                    ra[q] = fmaxf(ra[q] * s_scale[kb + q] + s_shift[kb + q], 0.f);
            }
        } else {
#pragma unroll
            for (int q = 0; q < 16; q++) ra[q] = 0.f;
        }
    };
    auto stsA = [&](int b) {
        char* ah = pAh(b);
        char* al = pAl(b);
#pragma unroll
        for (int j = 0; j < 8; j++) {
            float v0 = ra[2*j], v1 = ra[2*j+1], h0, h1;
            uint32_t hp = pack_hi(v0, v1, h0, h1);
            __nv_bfloat162 lo2 = __floats2bfloat162_rn(v0 - h0, v1 - h1);
            int boff = (arow * PA + ahalf + 2*j) * 2;
            *reinterpret_cast<uint32_t*>(ah + boff) = hp;
            *reinterpret_cast<uint32_t*>(al + boff) = *reinterpret_cast<uint32_t*>(&lo2);
        }
    };
    auto ldgB = [&](int c) {
#pragma unroll
        for (int q = 0; q < 3; q++) {
            int f4 = tid + q * 256;
            int rw = f4 >> 3;
            int kq = (f4 & 7) * 4;
            float4 f = *reinterpret_cast<const float4*>(&W[(size_t)rw * KD + c * KC + kq]);
            rb[q*4+0] = f.x; rb[q*4+1] = f.y; rb[q*4+2] = f.z; rb[q*4+3] = f.w;
        }
    };
    auto stsB = [&](int b) {
        char* bh = pBh(b);
        char* bl = pBl(b);
#pragma unroll
        for (int q = 0; q < 3; q++) {
            int f4 = tid + q * 256;
            int rw = f4 >> 3;
            int kq = (f4 & 7) * 4;
#pragma unroll
            for (int j = 0; j < 2; j++) {
                float v0 = rb[q*4 + 2*j], v1 = rb[q*4 + 2*j + 1], h0, h1;
                uint32_t hp = pack_hi(v0, v1, h0, h1);
                __nv_bfloat162 lo2 = __floats2bfloat162_rn(v0 - h0, v1 - h1);
                int boff = (rw * PA + kq + 2*j) * 2;
                *reinterpret_cast<uint32_t*>(bh + boff) = hp;
                *reinterpret_cast<uint32_t*>(bl + boff) = *reinterpret_cast<uint32_t*>(&lo2);
            }
        }
    };

    float acc[2][6][4];
#pragma unroll
    for (int mt = 0; mt < 2; mt++)
#pragma unroll
        for (int nt = 0; nt < 6; nt++)
#pragma unroll
            for (int q = 0; q < 4; q++) acc[mt][nt][q] = 0.f;

    auto compute = [&](int b) {
        const char* Ah = pAh(b);
        const char* Al = pAl(b);
        const char* Bh = pBh(b);
        const char* Bl = pBl(b);
#pragma unroll
        for (int kk = 0; kk < KC; kk += 16) {
            uint32_t ah[2][4], al[2][4], bh[6][2], bl[6][2];
#pragma unroll
            for (int mt = 0; mt < 2; mt++) {
                int r0 = warp_m * 32 + mt * 16 + g;
                int e0 = (r0 * PA + kk + t4 * 2) * 2;
                int e1 = ((r0 + 8) * PA + kk + t4 * 2) * 2;
                ah[mt][0] = *reinterpret_cast<const uint32_t*>(Ah + e0);
                ah[mt][1] = *reinterpret_cast<const uint32_t*>(Ah + e1);
                ah[mt][2] = *reinterpret_cast<const uint32_t*>(Ah + e0 + 16);
                ah[mt][3] = *reinterpret_cast<const uint32_t*>(Ah + e1 + 16);
                al[mt][0] = *reinterpret_cast<const uint32_t*>(Al + e0);
                al[mt][1] = *reinterpret_cast<const uint32_t*>(Al + e1);
                al[mt][2] = *reinterpret_cast<const uint32_t*>(Al + e0 + 16);
                al[mt][3] = *reinterpret_cast<const uint32_t*>(Al + e1 + 16);
            }
#pragma unroll
            for (int nt = 0; nt < 6; nt++) {
                int n = warp_n * 48 + nt * 8 + g;
                int e = (n * PA + kk + t4 * 2) * 2;
                bh[nt][0] = *reinterpret_cast<const uint32_t*>(Bh + e);
                bh[nt][1] = *reinterpret_cast<const uint32_t*>(Bh + e + 16);
                bl[nt][0] = *reinterpret_cast<const uint32_t*>(Bl + e);
                bl[nt][1] = *reinterpret_cast<const uint32_t*>(Bl + e + 16);
            }
#pragma unroll
            for (int mt = 0; mt < 2; mt++)
#pragma unroll
                for (int nt = 0; nt < 6; nt++) {
                    MMA(acc[mt][nt], ah[mt], bh[nt]);
                    MMA(acc[mt][nt], al[mt], bh[nt]);
                    MMA(acc[mt][nt], ah[mt], bl[nt]);
                }
        }
    };

    ldgA(0); ldgB(0);
    stsA(0); stsB(0);
    __syncthreads();
    for (int c = 0; c < NC; c++) {
        const bool pf = (c + 1 < NC);
        if (pf) { ldgA(c + 1); ldgB(c + 1); }
        compute(c & 1);
        if (pf) {
            stsA((c + 1) & 1); stsB((c + 1) & 1);
            __syncthreads();
        }
    }
    __syncthreads();

    // ---- epilogue: acc -> smem staging (pitch 100 floats) ----
    float* sD = (float*)(smem + OFF_A);
#pragma unroll
    for (int mt = 0; mt < 2; mt++) {
        int r0 = warp_m * 32 + mt * 16 + g;
#pragma unroll
        for (int nt = 0; nt < 6; nt++) {
            int cb = warp_n * 48 + nt * 8 + t4 * 2;
            sD[r0 * 100 + cb]       = acc[mt][nt][0];
            sD[r0 * 100 + cb + 1]   = acc[mt][nt][1];
            sD[(r0+8) * 100 + cb]   = acc[mt][nt][2];
            sD[(r0+8) * 100 + cb+1] = acc[mt][nt][3];
        }
    }
    __syncthreads();

    const int rmax = min(BM, N_NODES - row0);

    if (MODE == 1) {
        if (tid < H_DIM) {
            const float b = bias[tid];
            float s = 0.f, q = 0.f;
            for (int r = 0; r < rmax; r++) {
                float v = sD[r * 100 + tid] + b;
                s += v; q += v * v;
            }
            atomicAdd(&g_sum[tid],   s);
            atomicAdd(&g_sumsq[tid], q);
        }
    }

    for (int idx = tid; idx < rmax * 24; idx += 256) {
        int r = idx / 24, c4 = idx % 24;
        float4 v = *reinterpret_cast<const float4*>(&sD[r * 100 + c4 * 4]);
        float4 b = *reinterpret_cast<const float4*>(&bias[c4 * 4]);
        v.x += b.x; v.y += b.y; v.z += b.z; v.w += b.w;
        size_t o = (size_t)(row0 + r) * H_DIM + c4 * 4;
        if (MODE == 0) {
            *reinterpret_cast<float4*>(&g_h0[o]) = v;
            *reinterpret_cast<float4*>(&g_z [o]) = v;
        } else if (MODE == 1) {
            *reinterpret_cast<float4*>(&g_h[o]) = v;
        } else {
            *reinterpret_cast<float4*>(&out[o]) = v;
        }
    }
}

// =====================================================================
// Scatter-add  z[dst] += h0[src].  Block = 32 edges; indices staged in
// smem once; each thread: 3 col-groups (float4) of its edge.
// =====================================================================
__global__ __launch_bounds__(256) void k_scatter(const void* __restrict__ ei) {
    __shared__ int s_src[EPB], s_dst[EPB];
    const int tid = threadIdx.x;
    const int e0  = blockIdx.x * EPB;

    if (tid < 2 * EPB) {
        const int which = tid >> 5;          // 0: src, 1: dst
        const int i     = tid & 31;
        const int e     = e0 + i;
        int v = -1;
        if (e < N_EDGES) {
            const size_t off = which ? (size_t)N_EDGES + e : (size_t)e;
            v = g_is64 ? (int)((const long long*)ei)[off]
                       : ((const int*)ei)[off];
        }
        if (which) s_dst[i] = v; else s_src[i] = v;
    }
    __syncthreads();

    const int eL = tid >> 3;                 // 0..31
    const int c8 = tid & 7;                  // 0..7
    if (e0 + eL >= N_EDGES) return;
    const int src = s_src[eL];
    const int dst = s_dst[eL];
    if ((unsigned)src >= N_NODES || (unsigned)dst >= N_NODES) return;

    const float* srow = &g_h0[(size_t)src * H_DIM];
    float*       drow = &g_z [(size_t)dst * H_DIM];
#pragma unroll
    for (int j = 0; j < 3; j++) {
        const int c = (c8 + j * 8) * 4;
        const float4 v = *reinterpret_cast<const float4*>(srow + c);
        asm volatile("red.global.add.v4.f32 [%0], {%1,%2,%3,%4};"
                     :: "l"(drow + c), "f"(v.x), "f"(v.y), "f"(v.z), "f"(v.w)
                     : "memory");
    }
}

// =====================================================================
// launch
// =====================================================================
extern "C" void kernel_launch(void* const* d_in, const int* in_sizes, int n_in,
                              void* d_out, int out_size) {
    const float* x     = (const float*)d_in[0];
    const void*  ei    = d_in[1];
    const float* W0    = (const float*)d_in[2];
    const float* b0    = (const float*)d_in[3];
    const float* W1    = (const float*)d_in[4];
    const float* b1    = (const float*)d_in[5];
    const float* gamma = (const float*)d_in[6];
    const float* beta  = (const float*)d_in[7];
    const float* W2    = (const float*)d_in[8];
    const float* b2    = (const float*)d_in[9];
    float*       out   = (float*)d_out;

    static bool attr_done = false;
    if (!attr_done) {
        cudaFuncSetAttribute(k_tgemm<D_IN, 0>, cudaFuncAttributeMaxDynamicSharedMemorySize, SMEM_DYN);
        cudaFuncSetAttribute(k_tgemm<H_DIM, 1>, cudaFuncAttributeMaxDynamicSharedMemorySize, SMEM_DYN);
        cudaFuncSetAttribute(k_tgemm<H_DIM, 2>, cudaFuncAttributeMaxDynamicSharedMemorySize, SMEM_DYN);
        attr_done = true;
    }

    const int scat_blocks = (N_EDGES + EPB - 1) / EPB;   // 25000

    k_tgemm<D_IN, 0><<<N_BLK, 256, SMEM_DYN>>>(x, W0, b0, nullptr, (const int*)ei, nullptr, nullptr);
    k_scatter<<<scat_blocks, 256>>>(ei);
    k_tgemm<H_DIM, 1><<<N_BLK, 256, SMEM_DYN>>>(nullptr, W1, b1, nullptr, nullptr, nullptr, nullptr);
    k_tgemm<H_DIM, 2><<<N_BLK, 256, SMEM_DYN>>>(nullptr, W2, b2, out, nullptr, gamma, beta);
}